// round 11
// baseline (speedup 1.0000x reference)
#include <cuda_runtime.h>
#include <cuda_bf16.h>
#include <math.h>
#include <stdint.h>

#define NUM_FIELDS 32
#define FIELD_DIM  50000
#define EMB_DIM    64
#define ATT_DIM    32
#define NPAIRS     496
#define NTH        64
#define GRID_CTAS  1184

// ---- dynamic smem layout (bytes) ----
#define OFF_S      0       // 512 f32 (pads 496..511 = -1e30)
#define OFF_Q      2048    // 512 f32 (pads = 0)
#define OFF_RED    4096    // 8 f32: per-warp (mx, r, rb)
#define OFF_LUT    4128    // 512 u32 packed pair offsets
#define OFF_ET     6176    // Et[f][w]: 32 fields x 36 u32 (K-permuted bf16x2)
#define SMEM_TOTAL 10816
#define ET_FSTRIDE 144     // 36 words * 4B

typedef unsigned long long ull;

__device__ __forceinline__ uint32_t s2u(const void* p){
    uint32_t a; asm("{ .reg .u64 t; cvta.to.shared.u64 t, %1; cvt.u32.u64 %0, t; }":"=r"(a):"l"(p)); return a;
}
__device__ __forceinline__ uint32_t bfpair(float lo, float hi){
    uint32_t r; asm("cvt.rn.bf16x2.f32 %0, %1, %2;":"=r"(r):"f"(hi),"f"(lo)); return r;
}
__device__ __forceinline__ uint32_t mulbf2(uint32_t a, uint32_t b){
    uint32_t r; asm("mul.bf16x2 %0, %1, %2;":"=r"(r):"r"(a),"r"(b)); return r;
}
__device__ __forceinline__ uint32_t lds32(uint32_t a){
    uint32_t v; asm volatile("ld.shared.b32 %0, [%1];":"=r"(v):"r"(a)); return v;
}
__device__ __forceinline__ void lds128(uint32_t a, uint32_t* v){
    asm volatile("ld.shared.v4.b32 {%0,%1,%2,%3}, [%4];"
                 :"=r"(v[0]),"=r"(v[1]),"=r"(v[2]),"=r"(v[3]):"r"(a));
}
__device__ __forceinline__ void sts128(uint32_t a, uint32_t v0, uint32_t v1, uint32_t v2, uint32_t v3){
    asm volatile("st.shared.v4.b32 [%0], {%1,%2,%3,%4};"::"r"(a),"r"(v0),"r"(v1),"r"(v2),"r"(v3):"memory");
}
__device__ __forceinline__ void mma16816(float* c, uint32_t a0, uint32_t a1, uint32_t a2, uint32_t a3,
                                         uint32_t b0, uint32_t b1){
    asm volatile("mma.sync.aligned.m16n8k16.row.col.f32.bf16.bf16.f32 "
                 "{%0,%1,%2,%3}, {%4,%5,%6,%7}, {%8,%9}, {%0,%1,%2,%3};"
                 : "+f"(c[0]),"+f"(c[1]),"+f"(c[2]),"+f"(c[3])
                 : "r"(a0),"r"(a1),"r"(a2),"r"(a3),"r"(b0),"r"(b1));
}
// ---- packed f32x2 helpers ----
__device__ __forceinline__ ull pk2(float lo, float hi){
    ull r; asm("mov.b64 %0, {%1, %2};" : "=l"(r) : "f"(lo), "f"(hi)); return r;
}
__device__ __forceinline__ void upk2(ull v, float &lo, float &hi){
    asm("mov.b64 {%0, %1}, %2;" : "=f"(lo), "=f"(hi) : "l"(v));
}
__device__ __forceinline__ ull add2(ull a, ull b){
    ull d; asm("add.rn.f32x2 %0, %1, %2;" : "=l"(d) : "l"(a), "l"(b)); return d;
}
__device__ __forceinline__ void fma2(ull &d, ull a, ull b){
    asm("fma.rn.f32x2 %0, %1, %2, %0;" : "+l"(d) : "l"(a), "l"(b));
}
__device__ __forceinline__ ull and64(ull a, ull m){
    ull d; asm("and.b64 %0, %1, %2;" : "=l"(d) : "l"(a), "l"(m)); return d;
}

__device__ __forceinline__ void decode_pair(int p, int &i, int &j){
    int c = 31, ii = 0;
    while (p >= c) { p -= c; c--; ii++; }
    i = ii; j = ii + 1 + p;
}

__global__ __launch_bounds__(NTH, 8)
void afm_mma_kernel(const int*   __restrict__ x,
                    const float* __restrict__ emb,
                    const float* __restrict__ lin,
                    const float* __restrict__ lin_bias,
                    const float* __restrict__ W1,
                    const float* __restrict__ b1,
                    const float* __restrict__ w2,
                    const float* __restrict__ pw,
                    float*       __restrict__ out,
                    int BATCH)
{
    extern __shared__ char smem[];
    const uint32_t sb  = s2u(smem);
    const uint32_t etb = sb + OFF_ET;
    const int t    = threadIdx.x;
    const int wid  = t >> 5;     // 0 or 1
    const int lane = t & 31;

    float*    sS   = (float*)(smem + OFF_S);
    float*    sQ   = (float*)(smem + OFF_Q);
    float*    sRed = (float*)(smem + OFF_RED);
    uint32_t* sLUT = (uint32_t*)(smem + OFF_LUT);

    // ---- one-time init ----
    if (t < 16) { sS[496 + t] = -1e30f; sQ[496 + t] = 0.f; }
    for (int p = t; p < 512; p += NTH) {
        int pp = (p < NPAIRS) ? p : 0;
        int i, j; decode_pair(pp, i, j);
        sLUT[p] = (uint32_t)(i * ET_FSTRIDE) | ((uint32_t)(j * ET_FSTRIDE) << 16);
    }

    // ---- W1 (+ proj_w as n-tile 4) as permanent B-fragments (logical k indexing) ----
    uint32_t bfrag[5][4][2];
    {
        int n  = (lane >> 2);
        int kk = (lane & 3) * 2;
        #pragma unroll
        for (int ks = 0; ks < 4; ks++) {
            #pragma unroll
            for (int nt = 0; nt < 4; nt++) {
                int k = ks * 16 + kk, col = nt * 8 + n;
                bfrag[nt][ks][0] = bfpair(W1[(k    ) * 32 + col], W1[(k + 1) * 32 + col]);
                bfrag[nt][ks][1] = bfpair(W1[(k + 8) * 32 + col], W1[(k + 9) * 32 + col]);
            }
            int k = ks * 16 + kk;
            bfrag[4][ks][0] = (n == 0) ? bfpair(pw[k],     pw[k + 1]) : 0u;
            bfrag[4][ks][1] = (n == 0) ? bfpair(pw[k + 8], pw[k + 9]) : 0u;
        }
    }
    // packed epilogue constants: b1 pair and 0.5*w2 pair at this lane's C columns
    ull b1p[4], w2p[4];
    {
        int c0 = (lane & 3) * 2;
        #pragma unroll
        for (int nt = 0; nt < 4; nt++) {
            b1p[nt] = pk2(b1[nt * 8 + c0], b1[nt * 8 + c0 + 1]);
            w2p[nt] = pk2(0.5f * w2[nt * 8 + c0], 0.5f * w2[nt * 8 + c0 + 1]);
        }
    }
    const ull ABSM = 0x7FFFFFFF7FFFFFFFull;

    const float lbias = lin_bias[0];
    const int f = t >> 1, half = t & 1;
    const uint32_t ebase = etb + (uint32_t)(lane & 3) * 32;   // + 8*kk words
    const uint32_t lutb  = sb + OFF_LUT + ((uint32_t)(lane >> 2)) * 4;
    const uint32_t wbyte = etb + (uint32_t)f * 144 + (uint32_t)half * 16;

    __syncthreads();

    for (int b = blockIdx.x; b < BATCH; b += gridDim.x) {
        // ---- gather embeddings (MLP=8) -> K-permuted bf16x2 SMEM ----
        {
            int id = x[b * NUM_FIELDS + f] + f * FIELD_DIM;
            const float4* src = (const float4*)(emb + (size_t)id * EMB_DIM + half * 32);
            float4 v0 = src[0], v1 = src[1], v2 = src[2], v3 = src[3];
            float4 v4 = src[4], v5 = src[5], v6 = src[6], v7 = src[7];
            sts128(wbyte,       bfpair(v0.x,v0.y), bfpair(v2.x,v2.y), bfpair(v4.x,v4.y), bfpair(v6.x,v6.y));
            sts128(wbyte + 32,  bfpair(v0.z,v0.w), bfpair(v2.z,v2.w), bfpair(v4.z,v4.w), bfpair(v6.z,v6.w));
            sts128(wbyte + 64,  bfpair(v1.x,v1.y), bfpair(v3.x,v3.y), bfpair(v5.x,v5.y), bfpair(v7.x,v7.y));
            sts128(wbyte + 96,  bfpair(v1.z,v1.w), bfpair(v3.z,v3.w), bfpair(v5.z,v5.w), bfpair(v7.z,v7.w));
        }
        float firstv = 0.f;
        if (t < 32) {   // first-order linear term (fp32 exact)
            float v = lin[x[b * NUM_FIELDS + t] + t * FIELD_DIM];
            #pragma unroll
            for (int off = 16; off; off >>= 1) v += __shfl_down_sync(0xffffffffu, v, off);
            firstv = v + lbias;
        }
        __syncthreads();                                   // S1

        // ---- 16 M-tiles per warp (interleaved), 5 N-tiles, K=64 ----
        #pragma unroll
        for (int tl = 0; tl < 16; tl++) {
            const int base_t = (tl * 2 + wid) * 16;
            if (base_t >= NPAIRS) continue;                // tile 31 is pure padding
            uint32_t lo = lutb + (uint32_t)base_t * 4;
            uint32_t po1 = lds32(lo), po2 = lds32(lo + 32);

            uint32_t P1[8], P2[8];
            {
                uint32_t E[16];
                uint32_t ai = ebase + (po1 & 0xffffu), aj = ebase + (po1 >> 16);
                lds128(ai, E); lds128(ai + 16, E + 4);
                lds128(aj, E + 8); lds128(aj + 16, E + 12);
                #pragma unroll
                for (int c = 0; c < 8; c++) P1[c] = mulbf2(E[c], E[8 + c]);
                ai = ebase + (po2 & 0xffffu); aj = ebase + (po2 >> 16);
                lds128(ai, E); lds128(ai + 16, E + 4);
                lds128(aj, E + 8); lds128(aj + 16, E + 12);
                #pragma unroll
                for (int c = 0; c < 8; c++) P2[c] = mulbf2(E[c], E[8 + c]);
            }

            float acc[5][4];
            #pragma unroll
            for (int nt = 0; nt < 5; nt++)
                #pragma unroll
                for (int v = 0; v < 4; v++) acc[nt][v] = 0.f;

            #pragma unroll
            for (int ks = 0; ks < 4; ks++) {
                #pragma unroll
                for (int nt = 0; nt < 5; nt++)
                    mma16816(acc[nt], P1[2*ks], P2[2*ks], P1[2*ks+1], P2[2*ks+1],
                             bfrag[nt][ks][0], bfrag[nt][ks][1]);
            }

            // packed epilogue: sp = sum 0.5*w2 * ((t)+|t|), t = h+b1  (exact relu)
            #pragma unroll
            for (int rh = 0; rh < 2; rh++) {
                ull sp2 = 0ull;
                #pragma unroll
                for (int nt = 0; nt < 4; nt++) {
                    ull t2 = add2(pk2(acc[nt][rh * 2], acc[nt][rh * 2 + 1]), b1p[nt]);
                    ull u2 = add2(t2, and64(t2, ABSM));
                    fma2(sp2, w2p[nt], u2);
                }
                float slo, shi; upk2(sp2, slo, shi);
                float sp = slo + shi;
                sp += __shfl_xor_sync(0xffffffffu, sp, 1);
                sp += __shfl_xor_sync(0xffffffffu, sp, 2);
                int pair = base_t + rh * 8 + (lane >> 2);
                if ((lane & 3) == 0) {
                    sS[pair] = sp;
                    sQ[pair] = acc[4][rh * 2];
                }
            }
        }
        __syncthreads();                                   // S2

        // ---- per-warp softmax partials (own-max shift) over 256 values each ----
        {
            float sv[8], qv[8];
            float m = -1e30f;
            #pragma unroll
            for (int k = 0; k < 8; k++) {
                sv[k] = sS[t + 64 * k]; qv[k] = sQ[t + 64 * k];
                m = fmaxf(m, sv[k]);
            }
            #pragma unroll
            for (int off = 16; off; off >>= 1) m = fmaxf(m, __shfl_xor_sync(0xffffffffu, m, off));
            float r = 0.f, rb = 0.f;
            #pragma unroll
            for (int k = 0; k < 8; k++) {
                float e = __expf(sv[k] - m);
                r += e; rb = fmaf(e, qv[k], rb);
            }
            #pragma unroll
            for (int off = 16; off; off >>= 1) {
                r  += __shfl_xor_sync(0xffffffffu, r,  off);
                rb += __shfl_xor_sync(0xffffffffu, rb, off);
            }
            if (lane == 0) { sRed[wid * 3] = m; sRed[wid * 3 + 1] = r; sRed[wid * 3 + 2] = rb; }
        }
        __syncthreads();                                   // S3

        if (t == 0) {
            float MX = fmaxf(sRed[0], sRed[3]);
            float sc0 = __expf(sRed[0] - MX), sc1 = __expf(sRed[3] - MX);
            float R  = fmaf(sRed[1], sc0, sRed[4] * sc1);
            float RB = fmaf(sRed[2], sc0, sRed[5] * sc1);
            float y = firstv + RB / R;
            out[b] = 1.f / (1.f + __expf(-y));
        }
    }
}

extern "C" void kernel_launch(void* const* d_in, const int* in_sizes, int n_in,
                              void* d_out, int out_size)
{
    const int*   x   = (const int*)  d_in[0];
    const float* emb = (const float*)d_in[1];
    const float* lin = (const float*)d_in[2];
    const float* lb  = (const float*)d_in[3];
    const float* W1  = (const float*)d_in[4];
    const float* b1  = (const float*)d_in[5];
    const float* w2  = (const float*)d_in[6];
    const float* pwv = (const float*)d_in[7];
    const int B = in_sizes[0] / NUM_FIELDS;

    cudaFuncSetAttribute(afm_mma_kernel, cudaFuncAttributeMaxDynamicSharedMemorySize, SMEM_TOTAL);
    int grid = GRID_CTAS < B ? GRID_CTAS : B;
    afm_mma_kernel<<<grid, NTH, SMEM_TOTAL>>>(x, emb, lin, lb, W1, b1, w2, pwv, (float*)d_out, B);
}

// round 12
// speedup vs baseline: 1.0802x; 1.0802x over previous
#include <cuda_runtime.h>
#include <cuda_bf16.h>
#include <math.h>
#include <stdint.h>

#define NUM_FIELDS 32
#define FIELD_DIM  50000
#define EMB_DIM    64
#define ATT_DIM    32
#define NPAIRS     496
#define NTH        128
#define GRID_CTAS  592

// ---- dynamic smem layout (bytes) ----
#define OFF_S      0       // 512 f32 (pads 496..511 = -1e30)
#define OFF_Q      2048    // 512 f32 (pads = 0)
#define OFF_RED    4096    // 12 f32: per-warp (mx, r, rb)
#define OFF_LUT    4160    // 512 u32 packed pair offsets
#define OFF_ET     6208    // Et[f][w]: 32 fields x 36 u32 (K-permuted bf16x2)
#define SMEM_TOTAL 10816
#define ET_FSTRIDE 144     // 36 words * 4B

typedef unsigned long long ull;

__device__ __forceinline__ uint32_t s2u(const void* p){
    uint32_t a; asm("{ .reg .u64 t; cvta.to.shared.u64 t, %1; cvt.u32.u64 %0, t; }":"=r"(a):"l"(p)); return a;
}
__device__ __forceinline__ uint32_t bfpair(float lo, float hi){
    uint32_t r; asm("cvt.rn.bf16x2.f32 %0, %1, %2;":"=r"(r):"f"(hi),"f"(lo)); return r;
}
__device__ __forceinline__ uint32_t mulbf2(uint32_t a, uint32_t b){
    uint32_t r; asm("mul.bf16x2 %0, %1, %2;":"=r"(r):"r"(a),"r"(b)); return r;
}
__device__ __forceinline__ uint32_t lds32(uint32_t a){
    uint32_t v; asm volatile("ld.shared.b32 %0, [%1];":"=r"(v):"r"(a)); return v;
}
__device__ __forceinline__ void lds128(uint32_t a, uint32_t* v){
    asm volatile("ld.shared.v4.b32 {%0,%1,%2,%3}, [%4];"
                 :"=r"(v[0]),"=r"(v[1]),"=r"(v[2]),"=r"(v[3]):"r"(a));
}
__device__ __forceinline__ void sts64(uint32_t a, uint32_t v0, uint32_t v1){
    asm volatile("st.shared.v2.b32 [%0], {%1,%2};"::"r"(a),"r"(v0),"r"(v1):"memory");
}
__device__ __forceinline__ void mma16816(float* c, uint32_t a0, uint32_t a1, uint32_t a2, uint32_t a3,
                                         uint32_t b0, uint32_t b1){
    asm volatile("mma.sync.aligned.m16n8k16.row.col.f32.bf16.bf16.f32 "
                 "{%0,%1,%2,%3}, {%4,%5,%6,%7}, {%8,%9}, {%0,%1,%2,%3};"
                 : "+f"(c[0]),"+f"(c[1]),"+f"(c[2]),"+f"(c[3])
                 : "r"(a0),"r"(a1),"r"(a2),"r"(a3),"r"(b0),"r"(b1));
}
// ---- packed f32x2 helpers ----
__device__ __forceinline__ ull pk2(float lo, float hi){
    ull r; asm("mov.b64 %0, {%1, %2};" : "=l"(r) : "f"(lo), "f"(hi)); return r;
}
__device__ __forceinline__ void upk2(ull v, float &lo, float &hi){
    asm("mov.b64 {%0, %1}, %2;" : "=f"(lo), "=f"(hi) : "l"(v));
}
__device__ __forceinline__ ull add2(ull a, ull b){
    ull d; asm("add.rn.f32x2 %0, %1, %2;" : "=l"(d) : "l"(a), "l"(b)); return d;
}
__device__ __forceinline__ void fma2(ull &d, ull a, ull b){
    asm("fma.rn.f32x2 %0, %1, %2, %0;" : "+l"(d) : "l"(a), "l"(b));
}
__device__ __forceinline__ ull and64(ull a, ull m){
    ull d; asm("and.b64 %0, %1, %2;" : "=l"(d) : "l"(a), "l"(m)); return d;
}
__device__ __forceinline__ void decode_pair(int p, int &i, int &j){
    int c = 31, ii = 0;
    while (p >= c) { p -= c; c--; ii++; }
    i = ii; j = ii + 1 + p;
}

__global__ __launch_bounds__(NTH, 4)
void afm_mma_kernel(const int*   __restrict__ x,
                    const float* __restrict__ emb,
                    const float* __restrict__ lin,
                    const float* __restrict__ lin_bias,
                    const float* __restrict__ W1,
                    const float* __restrict__ b1,
                    const float* __restrict__ w2,
                    const float* __restrict__ pw,
                    float*       __restrict__ out,
                    int BATCH)
{
    extern __shared__ char smem[];
    const uint32_t sb  = s2u(smem);
    const uint32_t etb = sb + OFF_ET;
    const int t    = threadIdx.x;
    const int wid  = t >> 5;
    const int lane = t & 31;

    float*    sS   = (float*)(smem + OFF_S);
    float*    sQ   = (float*)(smem + OFF_Q);
    float*    sRed = (float*)(smem + OFF_RED);
    uint32_t* sLUT = (uint32_t*)(smem + OFF_LUT);
    uint32_t* sEt  = (uint32_t*)(smem + OFF_ET);

    // ---- one-time init ----
    if (t < 16) { sS[496 + t] = -1e30f; sQ[496 + t] = 0.f; }
    for (int p = t; p < 512; p += NTH) {
        int pp = (p < NPAIRS) ? p : 0;
        int i, j; decode_pair(pp, i, j);
        sLUT[p] = (uint32_t)(i * ET_FSTRIDE) | ((uint32_t)(j * ET_FSTRIDE) << 16);
    }

    // ---- W1 (+ proj_w as n-tile 4) as permanent B-fragments (logical k indexing) ----
    uint32_t bfrag[5][4][2];
    {
        int n  = (lane >> 2);
        int kk = (lane & 3) * 2;
        #pragma unroll
        for (int ks = 0; ks < 4; ks++) {
            #pragma unroll
            for (int nt = 0; nt < 4; nt++) {
                int k = ks * 16 + kk, col = nt * 8 + n;
                bfrag[nt][ks][0] = bfpair(W1[(k    ) * 32 + col], W1[(k + 1) * 32 + col]);
                bfrag[nt][ks][1] = bfpair(W1[(k + 8) * 32 + col], W1[(k + 9) * 32 + col]);
            }
            int k = ks * 16 + kk;
            bfrag[4][ks][0] = (n == 0) ? bfpair(pw[k],     pw[k + 1]) : 0u;
            bfrag[4][ks][1] = (n == 0) ? bfpair(pw[k + 8], pw[k + 9]) : 0u;
        }
    }
    // packed epilogue constants: b1 pair and 0.5*w2 pair at this lane's C columns
    ull b1p[4], w2p[4];
    {
        int c0 = (lane & 3) * 2;
        #pragma unroll
        for (int nt = 0; nt < 4; nt++) {
            b1p[nt] = pk2(b1[nt * 8 + c0], b1[nt * 8 + c0 + 1]);
            w2p[nt] = pk2(0.5f * w2[nt * 8 + c0], 0.5f * w2[nt * 8 + c0 + 1]);
        }
    }
    const ull ABSM = 0x7FFFFFFF7FFFFFFFull;

    const float lbias = lin_bias[0];
    const int f = t >> 2, q4 = t & 3;
    const uint32_t ebase = etb + (uint32_t)(lane & 3) * 32;   // + 8*kk words
    const uint32_t lutb  = sb + OFF_LUT + ((uint32_t)(lane >> 2)) * 4;

    // ---- prefetch first sample: 16 floats per thread (4 threads/field) ----
    float4 pf0, pf1, pf2, pf3; float pfl = 0.f;
    {
        int id = x[blockIdx.x * NUM_FIELDS + f] + f * FIELD_DIM;
        const float4* src = (const float4*)(emb + (size_t)id * EMB_DIM + q4 * 16);
        pf0 = src[0]; pf1 = src[1]; pf2 = src[2]; pf3 = src[3];
        if (t < 32) pfl = lin[x[blockIdx.x * NUM_FIELDS + t] + t * FIELD_DIM];
    }
    float firstv = 0.f;
    __syncthreads();

    for (int b = blockIdx.x; b < BATCH; b += gridDim.x) {
        // ---- store prefetched embeddings, K-permuted (phys word = 8*(l&3) + l/4) ----
        {
            uint32_t wb = etb + ((uint32_t)f * 36 + 2u * q4) * 4;
            sts64(wb,       bfpair(pf0.x, pf0.y), bfpair(pf2.x, pf2.y));
            sts64(wb + 32,  bfpair(pf0.z, pf0.w), bfpair(pf2.z, pf2.w));
            sts64(wb + 64,  bfpair(pf1.x, pf1.y), bfpair(pf3.x, pf3.y));
            sts64(wb + 96,  bfpair(pf1.z, pf1.w), bfpair(pf3.z, pf3.w));
        }
        if (t < 32) {   // first-order linear term (fp32 exact)
            float v = pfl;
            #pragma unroll
            for (int off = 16; off; off >>= 1) v += __shfl_down_sync(0xffffffffu, v, off);
            if (t == 0) firstv = v + lbias;
        }
        __syncthreads();                                   // S1

        // ---- prefetch next sample (hidden behind compute) ----
        {
            int nb = b + gridDim.x;
            if (nb < BATCH) {
                int id = x[nb * NUM_FIELDS + f] + f * FIELD_DIM;
                const float4* src = (const float4*)(emb + (size_t)id * EMB_DIM + q4 * 16);
                pf0 = src[0]; pf1 = src[1]; pf2 = src[2]; pf3 = src[3];
                if (t < 32) pfl = lin[x[nb * NUM_FIELDS + t] + t * FIELD_DIM];
            }
        }

        // ---- 8 M-tiles per warp (interleaved across warps), 5 N-tiles ----
        #pragma unroll
        for (int tl = 0; tl < 8; tl++) {
            const int base_t = (tl * 4 + wid) * 16;
            if (base_t >= NPAIRS) continue;                // tile 31 (tl=7,wid=3) = pure padding
            uint32_t lo = lutb + (uint32_t)base_t * 4;
            uint32_t po1 = lds32(lo), po2 = lds32(lo + 32);

            uint32_t P1[8], P2[8];
            {
                uint32_t E[16];
                uint32_t ai = ebase + (po1 & 0xffffu), aj = ebase + (po1 >> 16);
                lds128(ai, E); lds128(ai + 16, E + 4);
                lds128(aj, E + 8); lds128(aj + 16, E + 12);
                #pragma unroll
                for (int c = 0; c < 8; c++) P1[c] = mulbf2(E[c], E[8 + c]);
                ai = ebase + (po2 & 0xffffu); aj = ebase + (po2 >> 16);
                lds128(ai, E); lds128(ai + 16, E + 4);
                lds128(aj, E + 8); lds128(aj + 16, E + 12);
                #pragma unroll
                for (int c = 0; c < 8; c++) P2[c] = mulbf2(E[c], E[8 + c]);
            }

            float acc[5][4];
            #pragma unroll
            for (int nt = 0; nt < 5; nt++)
                #pragma unroll
                for (int v = 0; v < 4; v++) acc[nt][v] = 0.f;

            #pragma unroll
            for (int ks = 0; ks < 4; ks++) {
                #pragma unroll
                for (int nt = 0; nt < 5; nt++)
                    mma16816(acc[nt], P1[2*ks], P2[2*ks], P1[2*ks+1], P2[2*ks+1],
                             bfrag[nt][ks][0], bfrag[nt][ks][1]);
            }

            // packed epilogue: sp = sum 0.5*w2 * ((t)+|t|), t = h+b1  (exact relu)
            #pragma unroll
            for (int rh = 0; rh < 2; rh++) {
                ull sp2 = 0ull;
                #pragma unroll
                for (int nt = 0; nt < 4; nt++) {
                    ull t2 = add2(pk2(acc[nt][rh * 2], acc[nt][rh * 2 + 1]), b1p[nt]);
                    ull u2 = add2(t2, and64(t2, ABSM));
                    fma2(sp2, w2p[nt], u2);
                }
                float slo, shi; upk2(sp2, slo, shi);
                float sp = slo + shi;
                sp += __shfl_xor_sync(0xffffffffu, sp, 1);
                sp += __shfl_xor_sync(0xffffffffu, sp, 2);
                int pair = base_t + rh * 8 + (lane >> 2);
                if ((lane & 3) == 0 && pair < NPAIRS) {
                    sS[pair] = sp;
                    sQ[pair] = acc[4][rh * 2];
                }
            }
        }
        __syncthreads();                                   // S2

        // ---- per-warp softmax partials (own-max shift) ----
        {
            float s0 = sS[t], s1 = sS[t + 128], s2 = sS[t + 256], s3 = sS[t + 384];
            float q0 = sQ[t], q1 = sQ[t + 128], q2 = sQ[t + 256], q3 = sQ[t + 384];
            float m = fmaxf(fmaxf(s0, s1), fmaxf(s2, s3));
            #pragma unroll
            for (int off = 16; off; off >>= 1) m = fmaxf(m, __shfl_xor_sync(0xffffffffu, m, off));
            float e0 = __expf(s0 - m), e1 = __expf(s1 - m);
            float e2 = __expf(s2 - m), e3 = __expf(s3 - m);
            float r  = (e0 + e1) + (e2 + e3);
            float rb = fmaf(e0, q0, fmaf(e1, q1, fmaf(e2, q2, e3 * q3)));
            #pragma unroll
            for (int off = 16; off; off >>= 1) {
                r  += __shfl_xor_sync(0xffffffffu, r,  off);
                rb += __shfl_xor_sync(0xffffffffu, rb, off);
            }
            if (lane == 0) { sRed[wid * 3] = m; sRed[wid * 3 + 1] = r; sRed[wid * 3 + 2] = rb; }
        }
        __syncthreads();                                   // S3

        if (t == 0) {
            float MX = fmaxf(fmaxf(sRed[0], sRed[3]), fmaxf(sRed[6], sRed[9]));
            float R = 0.f, RB = 0.f;
            #pragma unroll
            for (int w = 0; w < 4; w++) {
                float sc = __expf(sRed[w * 3] - MX);
                R  = fmaf(sRed[w * 3 + 1], sc, R);
                RB = fmaf(sRed[w * 3 + 2], sc, RB);
            }
            float y = firstv + RB / R;
            out[b] = 1.f / (1.f + __expf(-y));
        }
    }
}

extern "C" void kernel_launch(void* const* d_in, const int* in_sizes, int n_in,
                              void* d_out, int out_size)
{
    const int*   x   = (const int*)  d_in[0];
    const float* emb = (const float*)d_in[1];
    const float* lin = (const float*)d_in[2];
    const float* lb  = (const float*)d_in[3];
    const float* W1  = (const float*)d_in[4];
    const float* b1  = (const float*)d_in[5];
    const float* w2  = (const float*)d_in[6];
    const float* pwv = (const float*)d_in[7];
    const int B = in_sizes[0] / NUM_FIELDS;

    cudaFuncSetAttribute(afm_mma_kernel, cudaFuncAttributeMaxDynamicSharedMemorySize, SMEM_TOTAL);
    int grid = GRID_CTAS < B ? GRID_CTAS : B;
    afm_mma_kernel<<<grid, NTH, SMEM_TOTAL>>>(x, emb, lin, lb, W1, b1, w2, pwv, (float*)d_out, B);
}